// round 8
// baseline (speedup 1.0000x reference)
#include <cuda_runtime.h>
#include <math.h>

#define Bsz 8
#define Esz 2000
#define Nsz 10000
#define NRELc 25
#define Ksz 16
#define Tsz 3
#define Lsz 32
#define TAU1f 10.0f
#define BL 256
#define MAXF 8192            // frontier capacity (expected ~1000)

// ---------------- scratch (static device globals; zero-initialized at load) ----------------
__device__ int      g_heads[Nsz];
__device__ int      g_tails[Nsz];
__device__ int      g_rels[Nsz];
__device__ int      g_hcnt[Esz];          // head-degree counts (zeroed each replay by prop_all)
__device__ int      g_hrow[Esz + 1];      // head-CSR rowptr
__device__ int      g_hfill[Esz];
__device__ unsigned g_trips[Nsz];         // tail(11b) | rel<<11, grouped by head
__device__ unsigned g_mask[Esz];          // relation bitmask per TAIL (zeroed each replay)
__device__ int      g_tidx[Esz];
__device__ int      g_ent[Bsz];
__device__ float    g_val[Bsz];
__device__ float    g_hx_acc[Bsz * NRELc];  // zeroed each replay
__device__ float    g_wp[Tsz * NRELc * Lsz];        // [t][r][l]
__device__ float    g_shp[Tsz * (NRELc - 1) * Lsz]; // [t][j][l]
__device__ float    g_shtp[Tsz * Ksz * Lsz];        // [t][k][l]
__device__ float    g_ab[Tsz * Lsz * 2];
__device__ float    g_tw[Lsz];
__device__ int2     g_metaA[MAXF];        // frontier meta (b, e)
__device__ int2     g_metaB[MAXF];
__device__ float    g_frA[MAXF * Lsz];    // frontier values
__device__ float    g_frB[MAXF * Lsz];

__device__ __forceinline__ float clip01(float x) { return fminf(fmaxf(x, 0.0f), 1.0f); }

// ============ 1) streaming extraction (161 MB) + head-degree counts ============
__global__ void k_setup(const float4* __restrict__ e2t,
                        const float4* __restrict__ t2e,
                        const float4* __restrict__ t2r,
                        const float*  __restrict__ input_x,
                        const float*  __restrict__ type_mat) {
    unsigned tid = blockIdx.x * blockDim.x + threadIdx.x;
    unsigned stride = gridDim.x * blockDim.x;

    for (unsigned i = tid; i < Bsz * Esz; i += stride) {
        float v = input_x[i];
        if (v != 0.0f) { g_ent[i / Esz] = (int)(i % Esz); g_val[i / Esz] = v; }
    }
    for (unsigned i = tid; i < Esz * Ksz; i += stride)
        if (type_mat[i] != 0.0f) g_tidx[i / Ksz] = (int)(i % Ksz);

    const unsigned n3 = Nsz * NRELc / 4;
    for (unsigned i = tid; i < n3; i += stride) {
        float4 v = t2r[i];
        unsigned base = i * 4u;
        if (v.x != 0.0f) { unsigned id = base + 0; g_rels[id / NRELc] = (int)(id % NRELc); }
        if (v.y != 0.0f) { unsigned id = base + 1; g_rels[id / NRELc] = (int)(id % NRELc); }
        if (v.z != 0.0f) { unsigned id = base + 2; g_rels[id / NRELc] = (int)(id % NRELc); }
        if (v.w != 0.0f) { unsigned id = base + 3; g_rels[id / NRELc] = (int)(id % NRELc); }
    }
    const unsigned n1 = (unsigned)Esz * Nsz / 4;   // e2triple [E,N] -> heads (+ degree)
    for (unsigned i = tid; i < n1; i += stride) {
        float4 v = e2t[i];
        unsigned base = i * 4u;
        if (v.x != 0.0f) { unsigned id = base + 0; int e = (int)(id / Nsz); g_heads[id % Nsz] = e; atomicAdd(&g_hcnt[e], 1); }
        if (v.y != 0.0f) { unsigned id = base + 1; int e = (int)(id / Nsz); g_heads[id % Nsz] = e; atomicAdd(&g_hcnt[e], 1); }
        if (v.z != 0.0f) { unsigned id = base + 2; int e = (int)(id / Nsz); g_heads[id % Nsz] = e; atomicAdd(&g_hcnt[e], 1); }
        if (v.w != 0.0f) { unsigned id = base + 3; int e = (int)(id / Nsz); g_heads[id % Nsz] = e; atomicAdd(&g_hcnt[e], 1); }
    }
    const unsigned n2 = (unsigned)Nsz * Esz / 4;   // triple2e [N,E] -> tails
    for (unsigned i = tid; i < n2; i += stride) {
        float4 v = t2e[i];
        unsigned base = i * 4u;
        if (v.x != 0.0f) { unsigned id = base + 0; g_tails[id / Esz] = (int)(id % Esz); }
        if (v.y != 0.0f) { unsigned id = base + 1; g_tails[id / Esz] = (int)(id % Esz); }
        if (v.z != 0.0f) { unsigned id = base + 2; g_tails[id / Esz] = (int)(id % Esz); }
        if (v.w != 0.0f) { unsigned id = base + 3; g_tails[id / Esz] = (int)(id % Esz); }
    }
}

// ============ 2) one block: scan head counts -> CSR rowptr; precompute tables ============
__global__ void __launch_bounds__(1024, 1)
k_scan(const float* __restrict__ alpha, const float* __restrict__ beta,
       const float* __restrict__ w, const float* __restrict__ h,
       const float* __restrict__ h_type, const float* __restrict__ weight) {
    __shared__ int sscan[1024];
    int t = threadIdx.x;

    // tables
    if (t < Tsz * Lsz) {
        int tt = t / Lsz, l = t % Lsz;
        const float* wr = w + (tt * Lsz + l) * NRELc;
        float m = -1e30f;
#pragma unroll
        for (int r = 0; r < NRELc; r++) m = fmaxf(m, wr[r]);
        float s = 0.0f, ev[NRELc];
#pragma unroll
        for (int r = 0; r < NRELc; r++) { ev[r] = expf(wr[r] - m); s += ev[r]; }
        float inv = 1.0f / s;
#pragma unroll
        for (int r = 0; r < NRELc; r++)
            g_wp[(tt * NRELc + r) * Lsz + l] = ev[r] * inv;
        g_ab[(tt * Lsz + l) * 2 + 0] = clip01(alpha[tt * Lsz + l] / TAU1f);
        g_ab[(tt * Lsz + l) * 2 + 1] = clip01(beta[tt * Lsz + l] / TAU1f);
    }
    for (int i = t; i < Tsz * (NRELc - 1) * Lsz; i += 1024) {
        int tt = i / ((NRELc - 1) * Lsz);
        int rem = i % ((NRELc - 1) * Lsz);
        int j = rem / Lsz, l = rem % Lsz;
        g_shp[i] = clip01(h[(tt * Lsz + l) * (NRELc - 1) + j] / TAU1f);
    }
    for (int i = t; i < Tsz * Ksz * Lsz; i += 1024) {
        int tt = i / (Ksz * Lsz);
        int rem = i % (Ksz * Lsz);
        int k = rem / Lsz, l = rem % Lsz;
        g_shtp[i] = clip01(h_type[(tt * Lsz + l) * Ksz + k] / TAU1f);
    }
    if (t < Lsz) g_tw[t] = tanhf(weight[t]);

    // exclusive scan of head counts
    int c0 = (2 * t < Esz) ? g_hcnt[2 * t] : 0;
    int c1 = (2 * t + 1 < Esz) ? g_hcnt[2 * t + 1] : 0;
    sscan[t] = c0 + c1;
    __syncthreads();
    for (int off = 1; off < 1024; off <<= 1) {
        int v = (t >= off) ? sscan[t - off] : 0;
        __syncthreads();
        sscan[t] += v;
        __syncthreads();
    }
    int excl = (t > 0) ? sscan[t - 1] : 0;
    if (2 * t < Esz)     { g_hrow[2 * t] = excl;          g_hfill[2 * t] = excl; }
    if (2 * t + 1 < Esz) { g_hrow[2 * t + 1] = excl + c0; g_hfill[2 * t + 1] = excl + c0; }
    if (t == 0) g_hrow[Esz] = Nsz;
}

// ============ 3) fill head-CSR + tail masks + hx join (grid-parallel) ============
__global__ void k_fill() {
    __shared__ int sent[Bsz];
    __shared__ float sval[Bsz];
    if (threadIdx.x < Bsz) { sent[threadIdx.x] = g_ent[threadIdx.x]; sval[threadIdx.x] = g_val[threadIdx.x]; }
    __syncthreads();
    for (int n = blockIdx.x * blockDim.x + threadIdx.x; n < Nsz; n += gridDim.x * blockDim.x) {
        int hd = g_heads[n], tl = g_tails[n], r = g_rels[n];
        int pos = atomicAdd(&g_hfill[hd], 1);
        g_trips[pos] = (unsigned)tl | ((unsigned)r << 11);
        if (r < NRELc - 1) atomicOr(&g_mask[tl], 1u << r);
#pragma unroll
        for (int b = 0; b < Bsz; b++)
            if (hd == sent[b]) atomicAdd(&g_hx_acc[b * NRELc + r], sval[b]);
    }
}

// ============ 4) single block: hx0 + full sparse 3-step expansion + out + cleanup ============
__global__ void __launch_bounds__(1024, 1)
k_prop_all(const float* __restrict__ alpha, const float* __restrict__ beta,
           const float* __restrict__ alpha_x, const float* __restrict__ beta_x,
           const float* __restrict__ h_x, const float* __restrict__ h_x_type,
           float* __restrict__ out) {
    __shared__ float s_hx0[BL];
    __shared__ int   sent[Bsz];
    __shared__ float sval[Bsz];
    __shared__ int   scnt0, scnt1, scnt2;

    const int t = threadIdx.x;
    const int wid = t >> 5, lane = t & 31;

    if (t < Bsz) { sent[t] = g_ent[t]; sval[t] = g_val[t]; }
    if (t == 0) { scnt0 = 0; scnt1 = 0; scnt2 = 0; }

    // zero the output (poisoned by harness)
    for (int i = t; i < Bsz * Esz; i += 1024) out[i] = 0.0f;
    __syncthreads();

    // hx0 per (b,l)
    if (t < BL) {
        int b = t / Lsz, l = t & 31;
        float a  = clip01(alpha[l] / TAU1f);
        float bb = clip01(beta[l] / TAU1f);
        float gate = 1.0f - clip01(clip01(alpha_x[l] / TAU1f) + clip01(beta_x[l] / TAU1f));
        float htx = clip01(h_x_type[l * Ksz + g_tidx[sent[b]]] / TAU1f) * sval[b];
        float hxl = 0.0f;
#pragma unroll
        for (int j = 0; j < NRELc - 1; j++) {
            int col = (j < 12) ? (12 + j) : (j - 12);
            hxl += clip01(g_hx_acc[b * NRELc + col]) * clip01(h_x[l * (NRELc - 1) + j] / TAU1f);
        }
        s_hx0[t] = clip01(a * htx + bb * hxl) + gate;
    }
    __syncthreads();

    // ---- frontier 0: expand the 8 one-hot entities through head-CSR, wp[0] ----
    if (wid < Bsz) {
        int b = wid, e = sent[b];
        int rb = g_hrow[e], re = g_hrow[e + 1];
        for (int j = rb; j < re; j++) {
            unsigned u = g_trips[j];
            int tail = u & 0x7ffu, rel = u >> 11;
            int idx;
            if (lane == 0) idx = atomicAdd(&scnt0, 1);
            idx = __shfl_sync(0xffffffffu, idx, 0);
            if (idx < MAXF) {
                if (lane == 0) g_metaA[idx] = make_int2(b, tail);
                g_frA[idx * Lsz + lane] = sval[b] * g_wp[(0 * NRELc + rel) * Lsz + lane];
            }
        }
    }
    __syncthreads();
    int cnt0 = min(scnt0, MAXF);

    // ---- expand step 1: apply hid0 * hx0 at consumption, wp[1] ----
    for (int i = wid; i < cnt0; i += 32) {
        int2 me = g_metaA[i];
        int b = me.x, e = me.y;
        float v = g_frA[i * Lsz + lane];
        float a  = g_ab[(0 * Lsz + lane) * 2 + 0];
        float bb = g_ab[(0 * Lsz + lane) * 2 + 1];
        float s1 = g_shtp[(0 * Ksz + g_tidx[e]) * Lsz + lane];
        float s2 = 0.0f;
        unsigned m = g_mask[e];
        while (m) { int jj = __ffs(m) - 1; s2 += g_shp[(0 * (NRELc - 1) + jj) * Lsz + lane]; m &= m - 1; }
        float hid = clip01(a * s1 + bb * s2) + (1.0f - clip01(a + bb));
        float f = v * hid * s_hx0[b * Lsz + lane];
        int rb = g_hrow[e], re = g_hrow[e + 1];
        for (int j = rb; j < re; j++) {
            unsigned u = g_trips[j];
            int tail = u & 0x7ffu, rel = u >> 11;
            int idx;
            if (lane == 0) idx = atomicAdd(&scnt1, 1);
            idx = __shfl_sync(0xffffffffu, idx, 0);
            if (idx < MAXF) {
                if (lane == 0) g_metaB[idx] = make_int2(b, tail);
                g_frB[idx * Lsz + lane] = f * g_wp[(1 * NRELc + rel) * Lsz + lane];
            }
        }
    }
    __syncthreads();
    int cnt1 = min(scnt1, MAXF);

    // ---- expand step 2: apply hid1 at consumption, wp[2] ----
    for (int i = wid; i < cnt1; i += 32) {
        int2 me = g_metaB[i];
        int b = me.x, e = me.y;
        float v = g_frB[i * Lsz + lane];
        float a  = g_ab[(1 * Lsz + lane) * 2 + 0];
        float bb = g_ab[(1 * Lsz + lane) * 2 + 1];
        float s1 = g_shtp[(1 * Ksz + g_tidx[e]) * Lsz + lane];
        float s2 = 0.0f;
        unsigned m = g_mask[e];
        while (m) { int jj = __ffs(m) - 1; s2 += g_shp[(1 * (NRELc - 1) + jj) * Lsz + lane]; m &= m - 1; }
        float hid = clip01(a * s1 + bb * s2) + (1.0f - clip01(a + bb));
        float f = v * hid;
        int rb = g_hrow[e], re = g_hrow[e + 1];
        for (int j = rb; j < re; j++) {
            unsigned u = g_trips[j];
            int tail = u & 0x7ffu, rel = u >> 11;
            int idx;
            if (lane == 0) idx = atomicAdd(&scnt2, 1);
            idx = __shfl_sync(0xffffffffu, idx, 0);
            if (idx < MAXF) {
                if (lane == 0) g_metaA[idx] = make_int2(b, tail);
                g_frA[idx * Lsz + lane] = f * g_wp[(2 * NRELc + rel) * Lsz + lane];
            }
        }
    }
    __syncthreads();
    int cnt2 = min(scnt2, MAXF);

    // ---- finalize: out[b,e] += sum_l v * hid2 * tanh(weight) ----
    for (int i = wid; i < cnt2; i += 32) {
        int2 me = g_metaA[i];
        int b = me.x, e = me.y;
        float v = g_frA[i * Lsz + lane];
        float a  = g_ab[(2 * Lsz + lane) * 2 + 0];
        float bb = g_ab[(2 * Lsz + lane) * 2 + 1];
        float s1 = g_shtp[(2 * Ksz + g_tidx[e]) * Lsz + lane];
        float s2 = 0.0f;
        unsigned m = g_mask[e];
        while (m) { int jj = __ffs(m) - 1; s2 += g_shp[(2 * (NRELc - 1) + jj) * Lsz + lane]; m &= m - 1; }
        float hid = clip01(a * s1 + bb * s2) + (1.0f - clip01(a + bb));
        float r = v * hid * g_tw[lane];
#pragma unroll
        for (int off = 16; off > 0; off >>= 1)
            r += __shfl_xor_sync(0xffffffffu, r, off);
        if (lane == 0) atomicAdd(&out[b * Esz + e], r);
    }
    __syncthreads();

    // ---- cleanup for next graph replay ----
    for (int i = t; i < Esz; i += 1024) { g_hcnt[i] = 0; g_mask[i] = 0u; }
    for (int i = t; i < Bsz * NRELc; i += 1024) g_hx_acc[i] = 0.0f;
}

// ---------------- launch ----------------
extern "C" void kernel_launch(void* const* d_in, const int* in_sizes, int n_in,
                              void* d_out, int out_size) {
    const float* input_x  = (const float*)d_in[0];
    const float* type_mat = (const float*)d_in[1];
    const float* e2triple = (const float*)d_in[2];
    const float* triple2e = (const float*)d_in[3];
    const float* triple2r = (const float*)d_in[4];
    const float* w        = (const float*)d_in[5];
    const float* weight   = (const float*)d_in[6];
    const float* h        = (const float*)d_in[7];
    const float* h_x      = (const float*)d_in[8];
    const float* h_type   = (const float*)d_in[9];
    const float* h_x_type = (const float*)d_in[10];
    const float* alpha    = (const float*)d_in[11];
    const float* beta     = (const float*)d_in[12];
    const float* alpha_x  = (const float*)d_in[13];
    const float* beta_x   = (const float*)d_in[14];
    float* out = (float*)d_out;

    k_setup<<<1184, 256>>>((const float4*)e2triple, (const float4*)triple2e,
                           (const float4*)triple2r, input_x, type_mat);
    k_scan<<<1, 1024>>>(alpha, beta, w, h, h_type, weight);
    k_fill<<<40, 256>>>();
    k_prop_all<<<1, 1024>>>(alpha, beta, alpha_x, beta_x, h_x, h_x_type, out);
}

// round 9
// speedup vs baseline: 1.2237x; 1.2237x over previous
#include <cuda_runtime.h>
#include <math.h>

#define Bsz 8
#define Esz 2000
#define Nsz 10000
#define NRELc 25
#define Ksz 16
#define Tsz 3
#define Lsz 32
#define TAU1f 10.0f
#define BL 256               // B*L columns
#define COL4 64              // BL/4 float4 columns
#define TPB 2                // tails per block
#define BMW 64               // bitmap words (2000 bits -> 63 words, round up)

// ---------------- scratch (static device globals) ----------------
__device__ int      g_heads[Nsz];
__device__ int      g_tails[Nsz];
__device__ int      g_rels[Nsz];
__device__ unsigned g_trips[Nsz];        // head(11b) | rel<<11, CSR by tail
__device__ int      g_rowptr[Esz + 1];
__device__ unsigned g_mask[Esz];         // 24-bit relation bitmask per tail
__device__ int      g_tidx[Esz];         // type index per entity
__device__ int      g_ent[Bsz];
__device__ float    g_val[Bsz];
__device__ float    g_hx0[BL];           // hidden_x at t=0, [b*32+l]
__device__ float    g_wp[Tsz * NRELc * Lsz];        // softmax(w[t]) stored [t][r][l]
__device__ float    g_shp[Tsz * (NRELc - 1) * Lsz]; // clip(h/10) [t][j][l]
__device__ float    g_shtp[Tsz * Ksz * Lsz];        // clip(h_type/10) [t][k][l]
__device__ float    g_ab[Tsz * Lsz * 2];            // a, bb per (t,l)
__device__ float    g_tw[Lsz];                      // tanh(weight)
__device__ unsigned g_bm0[BMW];          // possibly-nonzero rows of s0
__device__ unsigned g_bm1[BMW];          // possibly-nonzero rows of s1
__device__ float    g_sA[Esz * BL];      // s layout [e][b*32+l]
__device__ float    g_sB[Esz * BL];

__device__ __forceinline__ float clip01(float x) { return fminf(fmaxf(x, 0.0f), 1.0f); }

// ============ 1) streaming extraction of all one-hot structures ============
__global__ void k_setup(const float4* __restrict__ e2t,
                        const float4* __restrict__ t2e,
                        const float4* __restrict__ t2r,
                        const float*  __restrict__ input_x,
                        const float*  __restrict__ type_mat) {
    unsigned tid = blockIdx.x * blockDim.x + threadIdx.x;
    unsigned stride = gridDim.x * blockDim.x;

    for (unsigned i = tid; i < Bsz * Esz; i += stride) {
        float v = input_x[i];
        if (v != 0.0f) { g_ent[i / Esz] = (int)(i % Esz); g_val[i / Esz] = v; }
    }
    for (unsigned i = tid; i < Esz * Ksz; i += stride)
        if (type_mat[i] != 0.0f) g_tidx[i / Ksz] = (int)(i % Ksz);

    const unsigned n3 = Nsz * NRELc / 4;
    for (unsigned i = tid; i < n3; i += stride) {
        float4 v = t2r[i];
        unsigned base = i * 4u;
        if (v.x != 0.0f) { unsigned id = base + 0; g_rels[id / NRELc] = (int)(id % NRELc); }
        if (v.y != 0.0f) { unsigned id = base + 1; g_rels[id / NRELc] = (int)(id % NRELc); }
        if (v.z != 0.0f) { unsigned id = base + 2; g_rels[id / NRELc] = (int)(id % NRELc); }
        if (v.w != 0.0f) { unsigned id = base + 3; g_rels[id / NRELc] = (int)(id % NRELc); }
    }
    const unsigned n1 = (unsigned)Esz * Nsz / 4;   // e2triple [E,N] -> heads
    for (unsigned i = tid; i < n1; i += stride) {
        float4 v = e2t[i];
        unsigned base = i * 4u;
        if (v.x != 0.0f) { unsigned id = base + 0; g_heads[id % Nsz] = (int)(id / Nsz); }
        if (v.y != 0.0f) { unsigned id = base + 1; g_heads[id % Nsz] = (int)(id / Nsz); }
        if (v.z != 0.0f) { unsigned id = base + 2; g_heads[id % Nsz] = (int)(id / Nsz); }
        if (v.w != 0.0f) { unsigned id = base + 3; g_heads[id % Nsz] = (int)(id / Nsz); }
    }
    const unsigned n2 = (unsigned)Nsz * Esz / 4;   // triple2e [N,E] -> tails
    for (unsigned i = tid; i < n2; i += stride) {
        float4 v = t2e[i];
        unsigned base = i * 4u;
        if (v.x != 0.0f) { unsigned id = base + 0; g_tails[id / Esz] = (int)(id % Esz); }
        if (v.y != 0.0f) { unsigned id = base + 1; g_tails[id / Esz] = (int)(id % Esz); }
        if (v.z != 0.0f) { unsigned id = base + 2; g_tails[id / Esz] = (int)(id % Esz); }
        if (v.w != 0.0f) { unsigned id = base + 3; g_tails[id / Esz] = (int)(id % Esz); }
    }
}

// ============ 2) single block: join, bitmaps, scan, fill, tables, hx0 ============
__global__ void __launch_bounds__(1024, 1)
k_mid(const float* __restrict__ alpha, const float* __restrict__ beta,
      const float* __restrict__ alpha_x, const float* __restrict__ beta_x,
      const float* __restrict__ h_x, const float* __restrict__ h_x_type,
      const float* __restrict__ type_mat, const float* __restrict__ w,
      const float* __restrict__ h, const float* __restrict__ h_type,
      const float* __restrict__ weight) {
    __shared__ int      scnt[Esz];
    __shared__ unsigned smask[Esz];
    __shared__ int      sfill[Esz];
    __shared__ int      sscan[1024];
    __shared__ float    shx[Bsz * NRELc];
    __shared__ float    shxb[Bsz * (NRELc - 1)];
    __shared__ int      sent[Bsz];
    __shared__ float    sval[Bsz];
    __shared__ unsigned sbm0[BMW], sbm1[BMW];

    int t = threadIdx.x;
    for (int i = t; i < Esz; i += 1024) { scnt[i] = 0; smask[i] = 0u; }
    if (t < Bsz * NRELc) shx[t] = 0.0f;
    if (t < Bsz) { sent[t] = g_ent[t]; sval[t] = g_val[t]; }
    if (t < BMW) { sbm0[t] = 0u; sbm1[t] = 0u; }
    __syncthreads();

    // join pass: counts, masks, hx accumulation, bm0 (tails whose head is an input entity)
    for (int n = t; n < Nsz; n += 1024) {
        int tl = g_tails[n], r = g_rels[n], hd = g_heads[n];
        atomicAdd(&scnt[tl], 1);
        if (r < NRELc - 1) atomicOr(&smask[tl], 1u << r);
        bool hit = false;
#pragma unroll
        for (int b = 0; b < Bsz; b++)
            if (hd == sent[b]) { atomicAdd(&shx[b * NRELc + r], sval[b]); hit = true; }
        if (hit) atomicOr(&sbm0[tl >> 5], 1u << (tl & 31));
    }
    __syncthreads();

    // bm1: tails reachable from bm0 rows
    for (int n = t; n < Nsz; n += 1024) {
        int tl = g_tails[n], hd = g_heads[n];
        if ((sbm0[hd >> 5] >> (hd & 31)) & 1u)
            atomicOr(&sbm1[tl >> 5], 1u << (tl & 31));
    }
    __syncthreads();

    if (t < BMW) { g_bm0[t] = sbm0[t]; g_bm1[t] = sbm1[t]; }
    for (int i = t; i < Esz; i += 1024) g_mask[i] = smask[i];

    // ---- precompute tables ----
    if (t < Tsz * Lsz) {
        int tt = t / Lsz, l = t % Lsz;
        const float* wr = w + (tt * Lsz + l) * NRELc;
        float m = -1e30f;
#pragma unroll
        for (int r = 0; r < NRELc; r++) m = fmaxf(m, wr[r]);
        float s = 0.0f, ev[NRELc];
#pragma unroll
        for (int r = 0; r < NRELc; r++) { ev[r] = expf(wr[r] - m); s += ev[r]; }
        float inv = 1.0f / s;
#pragma unroll
        for (int r = 0; r < NRELc; r++)
            g_wp[(tt * NRELc + r) * Lsz + l] = ev[r] * inv;
        g_ab[(tt * Lsz + l) * 2 + 0] = clip01(alpha[tt * Lsz + l] / TAU1f);
        g_ab[(tt * Lsz + l) * 2 + 1] = clip01(beta[tt * Lsz + l] / TAU1f);
    }
    for (int i = t; i < Tsz * (NRELc - 1) * Lsz; i += 1024) {
        int tt = i / ((NRELc - 1) * Lsz);
        int rem = i % ((NRELc - 1) * Lsz);
        int j = rem / Lsz, l = rem % Lsz;
        g_shp[i] = clip01(h[(tt * Lsz + l) * (NRELc - 1) + j] / TAU1f);
    }
    for (int i = t; i < Tsz * Ksz * Lsz; i += 1024) {
        int tt = i / (Ksz * Lsz);
        int rem = i % (Ksz * Lsz);
        int k = rem / Lsz, l = rem % Lsz;
        g_shtp[i] = clip01(h_type[(tt * Lsz + l) * Ksz + k] / TAU1f);
    }
    if (t < Lsz) g_tw[t] = tanhf(weight[t]);

    // ---- exclusive scan ----
    int c0 = (2 * t < Esz) ? scnt[2 * t] : 0;
    int c1 = (2 * t + 1 < Esz) ? scnt[2 * t + 1] : 0;
    sscan[t] = c0 + c1;
    __syncthreads();
    for (int off = 1; off < 1024; off <<= 1) {
        int v = (t >= off) ? sscan[t - off] : 0;
        __syncthreads();
        sscan[t] += v;
        __syncthreads();
    }
    int excl = (t > 0) ? sscan[t - 1] : 0;
    if (2 * t < Esz)     { g_rowptr[2 * t] = excl;          sfill[2 * t] = excl; }
    if (2 * t + 1 < Esz) { g_rowptr[2 * t + 1] = excl + c0; sfill[2 * t + 1] = excl + c0; }
    if (t == 0) g_rowptr[Esz] = Nsz;

    if (t < Bsz * (NRELc - 1)) {
        int b = t / (NRELc - 1), j = t % (NRELc - 1);
        int col = (j < 12) ? (12 + j) : (j - 12);
        shxb[t] = clip01(shx[b * NRELc + col]);
    }
    __syncthreads();

    if (t < BL) {
        int b = t / Lsz, l = t % Lsz;
        float a  = clip01(alpha[l] / TAU1f);
        float bb = clip01(beta[l] / TAU1f);
        float gate = 1.0f - clip01(clip01(alpha_x[l] / TAU1f) + clip01(beta_x[l] / TAU1f));
        float htx = 0.0f;
#pragma unroll
        for (int k = 0; k < Ksz; k++)
            htx += type_mat[sent[b] * Ksz + k] * clip01(h_x_type[l * Ksz + k] / TAU1f);
        htx *= sval[b];
        float hxl = 0.0f;
#pragma unroll
        for (int j = 0; j < NRELc - 1; j++)
            hxl += shxb[b * (NRELc - 1) + j] * clip01(h_x[l * (NRELc - 1) + j] / TAU1f);
        g_hx0[t] = clip01(a * htx + bb * hxl) + gate;
    }
    __syncthreads();

    // counting-sort fill: head | rel<<11
    for (int n = t; n < Nsz; n += 1024) {
        int tl = g_tails[n];
        int pos = atomicAdd(&sfill[tl], 1);
        g_trips[pos] = (unsigned)g_heads[n] | ((unsigned)g_rels[n] << 11);
    }
}

// ============ 3) propagation: thread = 4 columns (float4), 2 tails/block ============
template <int T>
__global__ void __launch_bounds__(TPB * COL4)
k_prop(float* __restrict__ out) {
    const int tid = threadIdx.x;
    const int g = tid >> 6;          // local tail 0..1
    const int c = tid & 63;          // float4 column slot
    const int b = c >> 3;            // batch row for these 4 columns
    const int e0 = blockIdx.x * TPB;
    const int e  = e0 + g;

    __shared__ float shid[TPB][Lsz];
    __shared__ unsigned sbm[BMW];

    if (T >= 1 && tid < BMW) sbm[tid] = (T == 1) ? g_bm0[tid] : g_bm1[tid];

    // threads 0..63 compute the 2x32 distinct hidden[l,e] values
    if (tid < TPB * Lsz) {
        int gg = tid >> 5, l = tid & 31;
        int ee = e0 + gg;
        float a  = g_ab[(T * Lsz + l) * 2 + 0];
        float bb = g_ab[(T * Lsz + l) * 2 + 1];
        float s1 = g_shtp[(T * Ksz + g_tidx[ee]) * Lsz + l];
        float s2 = 0.0f;
        unsigned m = g_mask[ee];
        while (m) { int jj = __ffs(m) - 1; s2 += g_shp[(T * (NRELc - 1) + jj) * Lsz + l]; m &= m - 1; }
        shid[gg][l] = clip01(a * s1 + bb * s2) + (1.0f - clip01(a + bb));
    }
    __syncthreads();

    const float4* prevbuf = (const float4*)((T == 1) ? g_sA : g_sB);
    float4* dstbuf = (float4*)((T == 0) ? g_sA : g_sB);
    const float4* wp4 = (const float4*)g_wp;

    int sentb = 0; float svalb = 0.0f;
    if (T == 0) { sentb = g_ent[b]; svalb = g_val[b]; }

    const int beg = g_rowptr[e];
    const int end = g_rowptr[e + 1];

    float4 acc = make_float4(0.f, 0.f, 0.f, 0.f);
    int j = beg;
    unsigned u_next = (j < end) ? __ldg(&g_trips[j]) : 0u;
    while (j < end) {
        unsigned u = u_next;
        if (j + 1 < end) u_next = __ldg(&g_trips[j + 1]);
        unsigned head = u & 0x7ffu;
        unsigned rel  = u >> 11;
        if (T == 0) {
            if ((int)head == sentb) {
                float4 wv = wp4[(T * NRELc + rel) * 8 + (c & 7)];
                acc.x = fmaf(svalb, wv.x, acc.x);
                acc.y = fmaf(svalb, wv.y, acc.y);
                acc.z = fmaf(svalb, wv.z, acc.z);
                acc.w = fmaf(svalb, wv.w, acc.w);
            }
        } else {
            if ((sbm[head >> 5] >> (head & 31)) & 1u) {
                float4 v = prevbuf[head * COL4 + c];
                float4 wv = wp4[(T * NRELc + rel) * 8 + (c & 7)];
                acc.x = fmaf(v.x, wv.x, acc.x);
                acc.y = fmaf(v.y, wv.y, acc.y);
                acc.z = fmaf(v.z, wv.z, acc.z);
                acc.w = fmaf(v.w, wv.w, acc.w);
            }
        }
        ++j;
    }

    float4 hid = ((const float4*)shid[g])[c & 7];
    float4 val;
    if (T == 0) {
        float4 sc = ((const float4*)g_hx0)[c];
        val = make_float4(acc.x * hid.x * sc.x, acc.y * hid.y * sc.y,
                          acc.z * hid.z * sc.z, acc.w * hid.w * sc.w);
    } else {
        val = make_float4(acc.x * hid.x, acc.y * hid.y, acc.z * hid.z, acc.w * hid.w);
    }

    if (T == 2) {
        float4 tw = ((const float4*)g_tw)[c & 7];
        float r = val.x * tw.x + val.y * tw.y + val.z * tw.z + val.w * tw.w;
#pragma unroll
        for (int off = 4; off > 0; off >>= 1)
            r += __shfl_xor_sync(0xffffffffu, r, off);
        if ((c & 7) == 0) out[b * Esz + e] = r;
    } else {
        dstbuf[e * COL4 + c] = val;
    }
}

// ---------------- launch ----------------
extern "C" void kernel_launch(void* const* d_in, const int* in_sizes, int n_in,
                              void* d_out, int out_size) {
    const float* input_x  = (const float*)d_in[0];
    const float* type_mat = (const float*)d_in[1];
    const float* e2triple = (const float*)d_in[2];
    const float* triple2e = (const float*)d_in[3];
    const float* triple2r = (const float*)d_in[4];
    const float* w        = (const float*)d_in[5];
    const float* weight   = (const float*)d_in[6];
    const float* h        = (const float*)d_in[7];
    const float* h_x      = (const float*)d_in[8];
    const float* h_type   = (const float*)d_in[9];
    const float* h_x_type = (const float*)d_in[10];
    const float* alpha    = (const float*)d_in[11];
    const float* beta     = (const float*)d_in[12];
    const float* alpha_x  = (const float*)d_in[13];
    const float* beta_x   = (const float*)d_in[14];
    float* out = (float*)d_out;

    k_setup<<<1184, 256>>>((const float4*)e2triple, (const float4*)triple2e,
                           (const float4*)triple2r, input_x, type_mat);
    k_mid<<<1, 1024>>>(alpha, beta, alpha_x, beta_x, h_x, h_x_type,
                       type_mat, w, h, h_type, weight);
    k_prop<0><<<Esz / TPB, TPB * COL4>>>(out);
    k_prop<1><<<Esz / TPB, TPB * COL4>>>(out);
    k_prop<2><<<Esz / TPB, TPB * COL4>>>(out);
}